// round 10
// baseline (speedup 1.0000x reference)
#include <cuda_runtime.h>

// Problem dims (fixed)
#define T_DIM 100
#define B_DIM 128
#define F_DIM 4096
#define C_DIM 10

#define ROWS_PER_BLOCK 8          // consecutive (t,b) rows per block (same t)
#define RPAIRS (ROWS_PER_BLOCK / 2)
#define THREADS_K1 128
#define F4_DIM (F_DIM / 4)        // 1024 float4 per row
#define ITERS (F4_DIM / THREADS_K1)  // 8
#define OUTS (ROWS_PER_BLOCK * C_DIM) // 80
#define BC (B_DIM * C_DIM)        // 1280
#define GRID1 ((T_DIM * B_DIM) / ROWS_PER_BLOCK)  // 1600
#define SEQ_PER_THR (BC / THREADS_K1)             // 10

typedef unsigned long long u64;

// Packed f32x2 ops (Blackwell): one fma-pipe instruction, two fp32 lanes.
__device__ __forceinline__ u64 mul2(u64 a, u64 b) {
    u64 d; asm("mul.rn.f32x2 %0, %1, %2;" : "=l"(d) : "l"(a), "l"(b)); return d;
}
__device__ __forceinline__ u64 fma2(u64 a, u64 b, u64 c) {
    u64 d; asm("fma.rn.f32x2 %0, %1, %2, %3;" : "=l"(d) : "l"(a), "l"(b), "l"(c)); return d;
}
__device__ __forceinline__ u64 pack2(float lo, float hi) {
    u64 d; asm("mov.b64 %0, {%1, %2};" : "=l"(d) : "f"(lo), "f"(hi)); return d;
}
__device__ __forceinline__ void unpack2(u64 p, float& lo, float& hi) {
    asm("mov.b64 {%0, %1}, %2;" : "=f"(lo), "=f"(hi) : "l"(p));
}

// Scratch: current[t,b,c] in natural t-major layout [row][c] (512 KB).
__device__ float g_current[T_DIM * B_DIM * C_DIM];
// Completion counter for the fused-tail scan. Reset to 0 by the last block
// each run -> deterministic across graph replays.
__device__ int g_done = 0;

// ===================== Fused kernel: GEMV + tail scan =====================
// Phase A (all 1600 blocks): current[row][c] = 2*sum_f spike*mask*W[c,f] + b[c]
//   — EXACT Round-4 mainloop (proven 79us): row-paired f32x2, front-batched
//     __ldcs streaming loads, W L1-resident.
// Phase B (last block only, after atomic release/acquire): LIF scan over T
//   for all 1280 (b,c) sequences; runs during the other SMs' wave drain.
__global__ __launch_bounds__(THREADS_K1)
void snn_fused_kernel(const float* __restrict__ spike,
                      const float* __restrict__ mask,
                      const float* __restrict__ W,
                      const float* __restrict__ bias,
                      float* __restrict__ out)
{
    const int row0 = blockIdx.x * ROWS_PER_BLOCK;
    const int tid  = threadIdx.x;

    const float4* sp = reinterpret_cast<const float4*>(spike) + (size_t)row0 * F4_DIM;
    const float4* mk = reinterpret_cast<const float4*>(mask)  + (size_t)row0 * F4_DIM;
    const float4* W4 = reinterpret_cast<const float4*>(W);

    // acc2[rp][c]: lo lane = row 2*rp, hi lane = row 2*rp+1
    u64 acc2[RPAIRS][C_DIM];
#pragma unroll
    for (int rp = 0; rp < RPAIRS; ++rp)
#pragma unroll
        for (int c = 0; c < C_DIM; ++c)
            acc2[rp][c] = 0ull;

#pragma unroll
    for (int it = 0; it < ITERS; ++it) {
        const int f4 = tid + it * THREADS_K1;

        // Stream in 8 rows of spike+mask (evict-first so W stays L1-resident).
        float4 s4[ROWS_PER_BLOCK], m4[ROWS_PER_BLOCK];
#pragma unroll
        for (int r = 0; r < ROWS_PER_BLOCK; ++r) {
            s4[r] = __ldcs(&sp[(size_t)r * F4_DIM + f4]);
            m4[r] = __ldcs(&mk[(size_t)r * F4_DIM + f4]);
        }

        // x pairs: x[rp][fi] = { s*m (row 2rp), s*m (row 2rp+1) }
        u64 x[RPAIRS][4];
#pragma unroll
        for (int rp = 0; rp < RPAIRS; ++rp) {
            const float4 sa = s4[2 * rp], sb = s4[2 * rp + 1];
            const float4 ma = m4[2 * rp], mb = m4[2 * rp + 1];
            x[rp][0] = mul2(pack2(sa.x, sb.x), pack2(ma.x, mb.x));
            x[rp][1] = mul2(pack2(sa.y, sb.y), pack2(ma.y, mb.y));
            x[rp][2] = mul2(pack2(sa.z, sb.z), pack2(ma.z, mb.z));
            x[rp][3] = mul2(pack2(sa.w, sb.w), pack2(ma.w, mb.w));
        }

        // 10 W loads per iter amortized across 8 rows; lane-duplicate via
        // alu-pipe MOVs (overlaps with fma pipe). W stays L1-resident.
#pragma unroll
        for (int c = 0; c < C_DIM; ++c) {
            const float4 wv = __ldg(&W4[(size_t)c * F4_DIM + f4]);
            const u64 w0 = pack2(wv.x, wv.x);
            const u64 w1 = pack2(wv.y, wv.y);
            const u64 w2 = pack2(wv.z, wv.z);
            const u64 w3 = pack2(wv.w, wv.w);
#pragma unroll
            for (int rp = 0; rp < RPAIRS; ++rp) {
                u64 a = acc2[rp][c];
                a = fma2(x[rp][0], w0, a);
                a = fma2(x[rp][1], w1, a);
                a = fma2(x[rp][2], w2, a);
                a = fma2(x[rp][3], w3, a);
                acc2[rp][c] = a;
            }
        }
    }

    // Reduce: unpack pairs, warp shuffle, cross-warp smem.
    __shared__ float sred[THREADS_K1 / 32][OUTS];
    const int lane = tid & 31;
    const int warp = tid >> 5;

#pragma unroll
    for (int rp = 0; rp < RPAIRS; ++rp) {
#pragma unroll
        for (int c = 0; c < C_DIM; ++c) {
            float vlo, vhi;
            unpack2(acc2[rp][c], vlo, vhi);
#pragma unroll
            for (int o = 16; o > 0; o >>= 1) {
                vlo += __shfl_down_sync(0xffffffffu, vlo, o);
                vhi += __shfl_down_sync(0xffffffffu, vhi, o);
            }
            if (lane == 0) {
                sred[warp][(2 * rp) * C_DIM + c]     = vlo;
                sred[warp][(2 * rp + 1) * C_DIM + c] = vhi;
            }
        }
    }
    __syncthreads();

    // Epilogue: t-major store, contiguous 80 floats per block.
    if (tid < OUTS) {
        const float s = sred[0][tid] + sred[1][tid] + sred[2][tid] + sred[3][tid];
        const int c = tid % C_DIM;
        // 2.0f = 1/keep (dropout); bias added once.
        g_current[(size_t)row0 * C_DIM + tid] = 2.0f * s + bias[c];
    }

    // ---- Completion handoff: release stores, count arrivals ----
    __shared__ int s_last;
    __syncthreads();                 // block's g_current stores issued
    if (tid == 0) {
        __threadfence();             // release: make stores visible device-wide
        const int old = atomicAdd(&g_done, 1);
        s_last = (old == GRID1 - 1);
        if (s_last) g_done = 0;      // reset for next run (all adds done)
    }
    __syncthreads();
    if (!s_last) return;

    // ---- Phase B: LIF scan (last block only; 128 threads, 10 seq each) ----
    // v = 0.9v + cur; s = heaviside(v-1); v -= s.
    // Thread handles sequences idx = tid + 128*j. Loads/stores coalesced.
    float v[SEQ_PER_THR];
#pragma unroll
    for (int j = 0; j < SEQ_PER_THR; ++j) v[j] = 0.0f;

#pragma unroll 2
    for (int tc = 0; tc < T_DIM / 4; ++tc) {   // 4-t chunks: batch loads, then compute
        float cur[4][SEQ_PER_THR];
#pragma unroll
        for (int dt = 0; dt < 4; ++dt)
#pragma unroll
            for (int j = 0; j < SEQ_PER_THR; ++j)
                cur[dt][j] = g_current[(size_t)(4 * tc + dt) * BC + tid + THREADS_K1 * j];

#pragma unroll
        for (int dt = 0; dt < 4; ++dt) {
            const int t = 4 * tc + dt;
#pragma unroll
            for (int j = 0; j < SEQ_PER_THR; ++j) {
                v[j] = 0.9f * v[j] + cur[dt][j];
                const float s = (v[j] - 1.0f) > 0.0f ? 1.0f : 0.0f;
                out[(size_t)t * BC + tid + THREADS_K1 * j] = s;
                v[j] -= s;
            }
        }
    }
}

extern "C" void kernel_launch(void* const* d_in, const int* in_sizes, int n_in,
                              void* d_out, int out_size)
{
    const float* spike = (const float*)d_in[0];  // [T,B,F]
    const float* mask  = (const float*)d_in[1];  // [T,B,F]
    const float* W     = (const float*)d_in[2];  // [C,F]
    const float* bias  = (const float*)d_in[3];  // [C]
    float* out = (float*)d_out;                  // [T,B,C]

    snn_fused_kernel<<<GRID1, THREADS_K1>>>(spike, mask, W, bias, out);
}

// round 11
// speedup vs baseline: 1.2917x; 1.2917x over previous
#include <cuda_runtime.h>

// Problem dims (fixed)
#define T_DIM 100
#define B_DIM 128
#define F_DIM 4096
#define C_DIM 10

#define ROWS_PER_BLOCK 4          // consecutive (t,b) rows per block (same t)
#define RPAIRS (ROWS_PER_BLOCK / 2)
#define THREADS_K1 128
#define F4_DIM (F_DIM / 4)        // 1024 float4 per row
#define ITERS (F4_DIM / THREADS_K1)  // 8
#define OUTS (ROWS_PER_BLOCK * C_DIM) // 40
#define BC (B_DIM * C_DIM)        // 1280

typedef unsigned long long u64;

// Packed f32x2 ops (Blackwell): one fma-pipe instruction, two fp32 lanes.
__device__ __forceinline__ u64 mul2(u64 a, u64 b) {
    u64 d; asm("mul.rn.f32x2 %0, %1, %2;" : "=l"(d) : "l"(a), "l"(b)); return d;
}
__device__ __forceinline__ u64 fma2(u64 a, u64 b, u64 c) {
    u64 d; asm("fma.rn.f32x2 %0, %1, %2, %3;" : "=l"(d) : "l"(a), "l"(b), "l"(c)); return d;
}
__device__ __forceinline__ u64 pack2(float lo, float hi) {
    u64 d; asm("mov.b64 %0, {%1, %2};" : "=l"(d) : "f"(lo), "f"(hi)); return d;
}
__device__ __forceinline__ void unpack2(u64 p, float& lo, float& hi) {
    asm("mov.b64 {%0, %1}, %2;" : "=f"(lo), "=f"(hi) : "l"(p));
}

// Scratch for current, TRANSPOSED: g_currentT[(b*C + c) * T + t]  (512 KB)
__device__ float g_currentT[BC * T_DIM];

// ============================ Kernel 1: GEMV ============================
// current[t,b,c] = 2 * sum_f spike*mask*W[c,f] + bias[c]
// R4 recipe (front-batched __ldcs, row-paired f32x2, L1-resident W) with a
// LEAN register footprint: ROWS=4 -> 40-reg accumulators -> 4 CTAs/SM.
// Occupancy is the measured BW lever (R10: DRAM BW ~ linear in CTAs/SM).
__global__ __launch_bounds__(THREADS_K1, 4)
void snn_gemv_kernel(const float* __restrict__ spike,
                     const float* __restrict__ mask,
                     const float* __restrict__ W,
                     const float* __restrict__ bias)
{
    const int row0 = blockIdx.x * ROWS_PER_BLOCK;
    const int tid  = threadIdx.x;

    const float4* sp = reinterpret_cast<const float4*>(spike) + (size_t)row0 * F4_DIM;
    const float4* mk = reinterpret_cast<const float4*>(mask)  + (size_t)row0 * F4_DIM;
    const float4* W4 = reinterpret_cast<const float4*>(W);

    // acc2[rp][c]: lo lane = row 2*rp, hi lane = row 2*rp+1  (40 regs total)
    u64 acc2[RPAIRS][C_DIM];
#pragma unroll
    for (int rp = 0; rp < RPAIRS; ++rp)
#pragma unroll
        for (int c = 0; c < C_DIM; ++c)
            acc2[rp][c] = 0ull;

#pragma unroll
    for (int it = 0; it < ITERS; ++it) {
        const int f4 = tid + it * THREADS_K1;

        // Front-batch all 8 streaming loads (MLP_p1=8; evict-first keeps W in L1).
        float4 s4[ROWS_PER_BLOCK], m4[ROWS_PER_BLOCK];
#pragma unroll
        for (int r = 0; r < ROWS_PER_BLOCK; ++r) {
            s4[r] = __ldcs(&sp[(size_t)r * F4_DIM + f4]);
            m4[r] = __ldcs(&mk[(size_t)r * F4_DIM + f4]);
        }

        // x pairs: x[rp][fi] = { s*m (row 2rp), s*m (row 2rp+1) }
        u64 x[RPAIRS][4];
#pragma unroll
        for (int rp = 0; rp < RPAIRS; ++rp) {
            const float4 sa = s4[2 * rp], sb = s4[2 * rp + 1];
            const float4 ma = m4[2 * rp], mb = m4[2 * rp + 1];
            x[rp][0] = mul2(pack2(sa.x, sb.x), pack2(ma.x, mb.x));
            x[rp][1] = mul2(pack2(sa.y, sb.y), pack2(ma.y, mb.y));
            x[rp][2] = mul2(pack2(sa.z, sb.z), pack2(ma.z, mb.z));
            x[rp][3] = mul2(pack2(sa.w, sb.w), pack2(ma.w, mb.w));
        }

        // 10 W float4 L1 loads per iter amortized across 4 rows.
#pragma unroll
        for (int c = 0; c < C_DIM; ++c) {
            const float4 wv = __ldg(&W4[(size_t)c * F4_DIM + f4]);
            const u64 w0 = pack2(wv.x, wv.x);
            const u64 w1 = pack2(wv.y, wv.y);
            const u64 w2 = pack2(wv.z, wv.z);
            const u64 w3 = pack2(wv.w, wv.w);
#pragma unroll
            for (int rp = 0; rp < RPAIRS; ++rp) {
                u64 a = acc2[rp][c];
                a = fma2(x[rp][0], w0, a);
                a = fma2(x[rp][1], w1, a);
                a = fma2(x[rp][2], w2, a);
                a = fma2(x[rp][3], w3, a);
                acc2[rp][c] = a;
            }
        }
    }

    // Reduce: unpack pairs to per-row scalars, warp shuffle, cross-warp smem.
    __shared__ float sred[THREADS_K1 / 32][OUTS];
    const int lane = tid & 31;
    const int warp = tid >> 5;

#pragma unroll
    for (int rp = 0; rp < RPAIRS; ++rp) {
#pragma unroll
        for (int c = 0; c < C_DIM; ++c) {
            float vlo, vhi;
            unpack2(acc2[rp][c], vlo, vhi);
#pragma unroll
            for (int o = 16; o > 0; o >>= 1) {
                vlo += __shfl_down_sync(0xffffffffu, vlo, o);
                vhi += __shfl_down_sync(0xffffffffu, vhi, o);
            }
            if (lane == 0) {
                sred[warp][(2 * rp) * C_DIM + c]     = vlo;
                sred[warp][(2 * rp + 1) * C_DIM + c] = vhi;
            }
        }
    }
    __syncthreads();

    if (tid < OUTS) {
        const float s = sred[0][tid] + sred[1][tid] + sred[2][tid] + sred[3][tid];
        const int r = tid / C_DIM;
        const int c = tid % C_DIM;
        const int row = row0 + r;
        const int t = row / B_DIM;
        const int b = row % B_DIM;
        // 2.0f = 1/keep (dropout); bias added once. Transposed store.
        g_currentT[(size_t)(b * C_DIM + c) * T_DIM + t] = 2.0f * s + bias[c];
    }
}

// ============================ Kernel 2: scan ============================
// Proven R4 form (7.0us): 40 blocks x 32 threads, batch all 25 float4 loads
// up front (MLP=25), then run the serial LIF chain from registers/L1.
__global__ __launch_bounds__(32)
void snn_scan_kernel(float* __restrict__ out)
{
    const int idx = blockIdx.x * 32 + threadIdx.x;  // 0..1279
    if (idx >= BC) return;

    const float4* cur4 = reinterpret_cast<const float4*>(g_currentT + (size_t)idx * T_DIM);

    float vals[T_DIM];
#pragma unroll
    for (int i = 0; i < T_DIM / 4; ++i) {
        const float4 c4 = cur4[i];
        vals[4 * i + 0] = c4.x;
        vals[4 * i + 1] = c4.y;
        vals[4 * i + 2] = c4.z;
        vals[4 * i + 3] = c4.w;
    }

    float v = 0.0f;
#pragma unroll
    for (int t = 0; t < T_DIM; ++t) {
        v = 0.9f * v + vals[t];
        const float s = (v - 1.0f) > 0.0f ? 1.0f : 0.0f;
        out[(size_t)t * BC + idx] = s;   // coalesced across threads
        v -= s;
    }
}

extern "C" void kernel_launch(void* const* d_in, const int* in_sizes, int n_in,
                              void* d_out, int out_size)
{
    const float* spike = (const float*)d_in[0];  // [T,B,F]
    const float* mask  = (const float*)d_in[1];  // [T,B,F]
    const float* W     = (const float*)d_in[2];  // [C,F]
    const float* bias  = (const float*)d_in[3];  // [C]
    float* out = (float*)d_out;                  // [T,B,C]

    const int grid1 = (T_DIM * B_DIM) / ROWS_PER_BLOCK;  // 3200

    snn_gemv_kernel<<<grid1, THREADS_K1>>>(spike, mask, W, bias);

    snn_scan_kernel<<<BC / 32, 32>>>(out);               // 40 blocks x 32 thr
}